// round 5
// baseline (speedup 1.0000x reference)
#include <cuda_runtime.h>
#include <cstdint>

#define Bn 4
#define Ln 8192
#define Hn 128
#define Pn 64

typedef unsigned long long ull;

// Scratch (allocation-free rule: __device__ globals)
__device__ __align__(16) float g_Bu[Bn * Pn * Ln * 2];   // [b][p][l][(re,im)]
__device__ __align__(16) float g_ys[Bn * Pn * Ln * 2];   // [b][p][l][(re,im)]
__device__ __align__(16) float g_Bint[Pn * Hn * 2];      // [p][h][(re,im)]
__device__ __align__(16) float g_CT[Pn * Hn * 2];        // [p][h][(re,-im)]

// ---------- packed f32x2 helpers ----------
__device__ __forceinline__ ull dup2(float v) {
    ull r; unsigned uv = __float_as_uint(v);
    asm("mov.b64 %0, {%1, %1};" : "=l"(r) : "r"(uv));
    return r;
}
__device__ __forceinline__ ull pack2(float lo, float hi) {
    ull r;
    asm("mov.b64 %0, {%1, %2};" : "=l"(r) : "r"(__float_as_uint(lo)), "r"(__float_as_uint(hi)));
    return r;
}
__device__ __forceinline__ ull fma2(ull a, ull b, ull c) {
    ull d;
    asm("fma.rn.f32x2 %0, %1, %2, %3;" : "=l"(d) : "l"(a), "l"(b), "l"(c));
    return d;
}
__device__ __forceinline__ ull mul2(ull a, ull b) {
    ull d;
    asm("mul.rn.f32x2 %0, %1, %2;" : "=l"(d) : "l"(a), "l"(b));
    return d;
}
__device__ __forceinline__ void unpack2(ull v, float &lo, float &hi) {
    unsigned a, b;
    asm("mov.b64 {%0, %1}, %2;" : "=r"(a), "=r"(b) : "l"(v));
    lo = __uint_as_float(a); hi = __uint_as_float(b);
}

// ---------- Kernel 0: interleave weights ----------
__global__ __launch_bounds__(256) void k_prep(const float* __restrict__ Br,
                                              const float* __restrict__ Bi,
                                              const float* __restrict__ Cr,
                                              const float* __restrict__ Ci) {
    int i = blockIdx.x * 256 + threadIdx.x;    // 8192 elements each
    g_Bint[2 * i]     = Br[i];                 // Br is [P][H]: i = p*H + h
    g_Bint[2 * i + 1] = Bi[i];
    int h = i >> 6, p = i & 63;                // Cr is [H][P]
    g_CT[(p * Hn + h) * 2]     = Cr[i];
    g_CT[(p * Hn + h) * 2 + 1] = -Ci[i];
}

// ---------- Kernel 1: Bu[b][p][l][c] = sum_h u[l,h] * B_c[p,h] ----------
// f32x2 lanes = (l, l+1); re and im accumulate separately; B dup'd per (p,h).
#define UP 68    // u smem pitch: [128 h][64 l + pad]

__global__ __launch_bounds__(256, 3) void k_gemmB(const float* __restrict__ u) {
    __shared__ float su[128 * UP];            // 34,816 B
    const int b = blockIdx.y, lt = blockIdx.x;   // Ltile = 64
    const int tid = threadIdx.x;

    const float* ug = u + ((size_t)b * Ln + (size_t)lt * 64) * Hn;
    for (int e = tid; e < 64 * Hn; e += 256) {
        int l = e >> 7, h = e & 127;
        su[h * UP + l] = ug[e];
    }
    __syncthreads();

    const int tx = tid & 7, ty = tid >> 3;      // ty 0..31
    const int lA = tx * 4, lB = 32 + tx * 4;
    const int p0 = ty * 2;

    ull accRe[2][4], accIm[2][4];
#pragma unroll
    for (int p = 0; p < 2; ++p)
#pragma unroll
        for (int k = 0; k < 4; ++k) { accRe[p][k] = 0; accIm[p][k] = 0; }

    const float* suA = su + lA;
    const float* suB = su + lB;
    const float4* __restrict__ B0 = (const float4*)(g_Bint + p0 * 2 * Hn);
    const float4* __restrict__ B1 = (const float4*)(g_Bint + (p0 + 1) * 2 * Hn);

#pragma unroll 2
    for (int h = 0; h < Hn; h += 2) {
        ulonglong2 uA0 = *(const ulonglong2*)(suA + h * UP);
        ulonglong2 uB0 = *(const ulonglong2*)(suB + h * UP);
        ulonglong2 uA1 = *(const ulonglong2*)(suA + (h + 1) * UP);
        ulonglong2 uB1 = *(const ulonglong2*)(suB + (h + 1) * UP);
        float4 bv0 = B0[h >> 1];
        float4 bv1 = B1[h >> 1];
        ull r0h = dup2(bv0.x), i0h = dup2(bv0.y), r0g = dup2(bv0.z), i0g = dup2(bv0.w);
        ull r1h = dup2(bv1.x), i1h = dup2(bv1.y), r1g = dup2(bv1.z), i1g = dup2(bv1.w);

        accRe[0][0] = fma2(uA0.x, r0h, accRe[0][0]); accRe[0][0] = fma2(uA1.x, r0g, accRe[0][0]);
        accRe[0][1] = fma2(uA0.y, r0h, accRe[0][1]); accRe[0][1] = fma2(uA1.y, r0g, accRe[0][1]);
        accRe[0][2] = fma2(uB0.x, r0h, accRe[0][2]); accRe[0][2] = fma2(uB1.x, r0g, accRe[0][2]);
        accRe[0][3] = fma2(uB0.y, r0h, accRe[0][3]); accRe[0][3] = fma2(uB1.y, r0g, accRe[0][3]);
        accIm[0][0] = fma2(uA0.x, i0h, accIm[0][0]); accIm[0][0] = fma2(uA1.x, i0g, accIm[0][0]);
        accIm[0][1] = fma2(uA0.y, i0h, accIm[0][1]); accIm[0][1] = fma2(uA1.y, i0g, accIm[0][1]);
        accIm[0][2] = fma2(uB0.x, i0h, accIm[0][2]); accIm[0][2] = fma2(uB1.x, i0g, accIm[0][2]);
        accIm[0][3] = fma2(uB0.y, i0h, accIm[0][3]); accIm[0][3] = fma2(uB1.y, i0g, accIm[0][3]);

        accRe[1][0] = fma2(uA0.x, r1h, accRe[1][0]); accRe[1][0] = fma2(uA1.x, r1g, accRe[1][0]);
        accRe[1][1] = fma2(uA0.y, r1h, accRe[1][1]); accRe[1][1] = fma2(uA1.y, r1g, accRe[1][1]);
        accRe[1][2] = fma2(uB0.x, r1h, accRe[1][2]); accRe[1][2] = fma2(uB1.x, r1g, accRe[1][2]);
        accRe[1][3] = fma2(uB0.y, r1h, accRe[1][3]); accRe[1][3] = fma2(uB1.y, r1g, accRe[1][3]);
        accIm[1][0] = fma2(uA0.x, i1h, accIm[1][0]); accIm[1][0] = fma2(uA1.x, i1g, accIm[1][0]);
        accIm[1][1] = fma2(uA0.y, i1h, accIm[1][1]); accIm[1][1] = fma2(uA1.y, i1g, accIm[1][1]);
        accIm[1][2] = fma2(uB0.x, i1h, accIm[1][2]); accIm[1][2] = fma2(uB1.x, i1g, accIm[1][2]);
        accIm[1][3] = fma2(uB0.y, i1h, accIm[1][3]); accIm[1][3] = fma2(uB1.y, i1g, accIm[1][3]);
    }

#pragma unroll
    for (int p = 0; p < 2; ++p) {
        size_t base = ((size_t)(b * Pn + p0 + p) * Ln + (size_t)lt * 64) * 2;
#pragma unroll
        for (int k = 0; k < 4; ++k) {
            int l = (k < 2) ? (lA + 2 * k) : (lB + 2 * (k - 2));
            float r0, r1, i0, i1;
            unpack2(accRe[p][k], r0, r1);
            unpack2(accIm[p][k], i0, i1);
            *(ulonglong2*)&g_Bu[base + 2 * l] =
                make_ulonglong2(pack2(r0, i0), pack2(r1, i1));
        }
    }
}

// ---------- Kernel 2: chunked linear-recurrence scan (f32x2 packed re/im) ----------
__global__ __launch_bounds__(512) void k_recur(const float* __restrict__ A_diag,
                                               const float* __restrict__ steps) {
    const int p = blockIdx.x, b = blockIdx.y;
    const int t = threadIdx.x;

    float a  = fmaxf(A_diag[p], 0.f);
    float s  = 1.f / (1.f + expf(-steps[p]));
    float s2a   = s * s * a;
    float schur = 1.f / (1.f + s2a);
    float m11 = 1.f - s2a * schur;
    float m12 = -s * a * schur;
    float m21 = s * schur;
    float m22 = schur;
    ull M11 = dup2(m11), M12 = dup2(m12), M21 = dup2(m21), M22 = dup2(m22);
    ull C1 = dup2(m11 * s), C2 = dup2(m21 * s);

    const size_t chain = (size_t)(b * Pn + p);
    const ulonglong2* src = (const ulonglong2*)(g_Bu) + chain * (Ln / 2) + t * 8;

    ull f[16];
#pragma unroll
    for (int k = 0; k < 8; ++k) {
        ulonglong2 v = src[k];
        f[2 * k] = v.x; f[2 * k + 1] = v.y;
    }

    ull z = 0, x = 0;
#pragma unroll
    for (int i = 0; i < 16; ++i) {
        ull nz = fma2(M11, z, fma2(M12, x, mul2(C1, f[i])));
        ull nx = fma2(M21, z, fma2(M22, x, mul2(C2, f[i])));
        z = nz; x = nx;
    }

    float q00 = m11, q01 = m12, q10 = m21, q11 = m22;
#pragma unroll
    for (int k = 0; k < 4; ++k) {
        float n00 = q00*q00 + q01*q10, n01 = q00*q01 + q01*q11;
        float n10 = q10*q00 + q11*q10, n11 = q10*q01 + q11*q11;
        q00 = n00; q01 = n01; q10 = n10; q11 = n11;
    }

    __shared__ ulonglong2 sv[512];
    ull vz = z, vx = x;
    int off = 1;
#pragma unroll
    for (int st = 0; st < 9; ++st) {
        sv[t] = make_ulonglong2(vz, vx);
        __syncthreads();
        if (t >= off) {
            ulonglong2 w = sv[t - off];
            ull Q00 = dup2(q00), Q01 = dup2(q01), Q10 = dup2(q10), Q11 = dup2(q11);
            ull nvz = fma2(Q00, w.x, fma2(Q01, w.y, vz));
            ull nvx = fma2(Q10, w.x, fma2(Q11, w.y, vx));
            vz = nvz; vx = nvx;
        }
        __syncthreads();
        float n00 = q00*q00 + q01*q10, n01 = q00*q01 + q01*q11;
        float n10 = q10*q00 + q11*q10, n11 = q10*q01 + q11*q11;
        q00 = n00; q01 = n01; q10 = n10; q11 = n11;
        off <<= 1;
    }
    sv[t] = make_ulonglong2(vz, vx);
    __syncthreads();
    ull z0 = 0, x0 = 0;
    if (t > 0) { ulonglong2 w = sv[t - 1]; z0 = w.x; x0 = w.y; }

    z = z0; x = x0;
#pragma unroll
    for (int i = 0; i < 16; ++i) {
        ull nz = fma2(M11, z, fma2(M12, x, mul2(C1, f[i])));
        ull nx = fma2(M21, z, fma2(M22, x, mul2(C2, f[i])));
        z = nz; x = nx;
        f[i] = x;
    }
    ulonglong2* dst = (ulonglong2*)(g_ys) + chain * (Ln / 2) + t * 8;
#pragma unroll
    for (int k = 0; k < 8; ++k) dst[k] = make_ulonglong2(f[2 * k], f[2 * k + 1]);
}

// ---------- Kernel 3: y = ys_re @ Cr^T - ys_im @ Ci^T + D*u ----------
// Ltile=128, Htile=64; thread tile 4 l x 8 h; y via smem (2 LDS.128 / p),
// C streamed via uniform LDG.128 from L1-resident g_CT.
__global__ __launch_bounds__(256, 2) void k_gemmD(const float* __restrict__ u,
                                                  const float* __restrict__ Dv,
                                                  float* __restrict__ out) {
    extern __shared__ float sy[];   // [64 p][128 l][(re,im)] = 65536 B
    const int b = blockIdx.y, lt = blockIdx.x, hh = blockIdx.z;
    const int tid = threadIdx.x;
    const int tx = tid & 31, ty = tid >> 5;      // 32 x 8
    const int h0 = hh * 64 + ty * 8;

    // stage y tile: 4096 ulonglong2 units, fully coalesced
    {
        const ulonglong2* __restrict__ ysrc = (const ulonglong2*)(g_ys);
        ulonglong2* __restrict__ sdst = (ulonglong2*)sy;
        for (int e = tid; e < Pn * 64; e += 256) {
            int p = e >> 6, g = e & 63;
            sdst[p * 64 + g] = ysrc[((size_t)(b * Pn + p) * Ln + (size_t)lt * 128) / 2 + g];
        }
    }
    __syncthreads();

    ull acc[4][8];   // [l: 2tx,2tx+1,64+2tx,65+2tx][h0..h0+7]
#pragma unroll
    for (int i = 0; i < 4; ++i)
#pragma unroll
        for (int j = 0; j < 8; ++j) acc[i][j] = 0;

    const ulonglong2* __restrict__ CT2 = (const ulonglong2*)(g_CT);
    const float* syA = sy + 4 * tx;          // l pair (2tx, 2tx+1)      -> floats p*256 + 4tx
    const float* syB = sy + 128 + 4 * tx;    // l pair (64+2tx, 65+2tx)  -> floats p*256 + 128 + 4tx

#pragma unroll 2
    for (int p = 0; p < Pn; ++p) {
        ulonglong2 ya = *(const ulonglong2*)(syA + p * 256);
        ulonglong2 yb = *(const ulonglong2*)(syB + p * 256);
        int cb = (p * Hn + h0) >> 1;        // ulonglong2 index into g_CT
        ulonglong2 c01 = CT2[cb];
        ulonglong2 c23 = CT2[cb + 1];
        ulonglong2 c45 = CT2[cb + 2];
        ulonglong2 c67 = CT2[cb + 3];
        ull c[8] = {c01.x, c01.y, c23.x, c23.y, c45.x, c45.y, c67.x, c67.y};
#pragma unroll
        for (int j = 0; j < 8; ++j) {
            acc[0][j] = fma2(ya.x, c[j], acc[0][j]);
            acc[1][j] = fma2(ya.y, c[j], acc[1][j]);
            acc[2][j] = fma2(yb.x, c[j], acc[2][j]);
            acc[3][j] = fma2(yb.y, c[j], acc[3][j]);
        }
    }

    float4 d0 = *(const float4*)&Dv[h0];
    float4 d1 = *(const float4*)&Dv[h0 + 4];
    float dv[8] = {d0.x, d0.y, d0.z, d0.w, d1.x, d1.y, d1.z, d1.w};

#pragma unroll
    for (int i = 0; i < 4; ++i) {
        int l = (i < 2) ? (2 * tx + i) : (64 + 2 * tx + (i - 2));
        size_t row = ((size_t)b * Ln + (size_t)lt * 128 + l) * Hn + h0;
        float4 u0 = *(const float4*)&u[row];
        float4 u1 = *(const float4*)&u[row + 4];
        float uv[8] = {u0.x, u0.y, u0.z, u0.w, u1.x, u1.y, u1.z, u1.w};
        float y[8];
#pragma unroll
        for (int j = 0; j < 8; ++j) {
            float lo, hi; unpack2(acc[i][j], lo, hi);
            y[j] = lo + hi + dv[j] * uv[j];
        }
        *(float4*)&out[row]     = make_float4(y[0], y[1], y[2], y[3]);
        *(float4*)&out[row + 4] = make_float4(y[4], y[5], y[6], y[7]);
    }
}

// ---------- launch ----------
extern "C" void kernel_launch(void* const* d_in, const int* in_sizes, int n_in,
                              void* d_out, int out_size) {
    const float* u     = (const float*)d_in[0];
    const float* A_d   = (const float*)d_in[1];
    const float* Br    = (const float*)d_in[2];
    const float* Bi    = (const float*)d_in[3];
    const float* Cr    = (const float*)d_in[4];
    const float* Ci    = (const float*)d_in[5];
    const float* Dv    = (const float*)d_in[6];
    const float* steps = (const float*)d_in[7];
    float* out = (float*)d_out;

    const int SMD = Pn * 128 * 2 * 4;   // 65536 B
    cudaFuncSetAttribute(k_gemmD, cudaFuncAttributeMaxDynamicSharedMemorySize, SMD);

    k_prep<<<32, 256>>>(Br, Bi, Cr, Ci);
    k_gemmB<<<dim3(Ln / 64, Bn), 256>>>(u);
    k_recur<<<dim3(Pn, Bn), 512>>>(A_d, steps);
    k_gemmD<<<dim3(Ln / 128, Bn, 2), 256, SMD>>>(u, Dv, out);
}

// round 8
// speedup vs baseline: 1.6100x; 1.6100x over previous
#include <cuda_runtime.h>
#include <cuda_bf16.h>
#include <cstdint>

#define Bn 4
#define Ln 8192
#define Hn 128
#define Pn 64

typedef unsigned long long ull;

// ---------------- global scratch ----------------
__device__ __align__(16) float g_Bu[Bn * Pn * Ln * 2];   // [b][p][l][(re,im)]
__device__ __align__(16) float g_ys[Bn * Pn * Ln * 2];   // [b][p][l][(re,im)]
// pre-split, pre-swizzled bf16 weight tiles (128 rows x 128 cols, 32KB each)
__device__ __align__(16) unsigned char g_WBh[32768];
__device__ __align__(16) unsigned char g_WBl[32768];
__device__ __align__(16) unsigned char g_WCh[32768];
__device__ __align__(16) unsigned char g_WCl[32768];

// ---------------- f32x2 helpers (scan) ----------------
__device__ __forceinline__ ull dup2(float v) {
    ull r; unsigned uv = __float_as_uint(v);
    asm("mov.b64 %0, {%1, %1};" : "=l"(r) : "r"(uv));
    return r;
}
__device__ __forceinline__ ull fma2(ull a, ull b, ull c) {
    ull d;
    asm("fma.rn.f32x2 %0, %1, %2, %3;" : "=l"(d) : "l"(a), "l"(b), "l"(c));
    return d;
}
__device__ __forceinline__ ull mul2(ull a, ull b) {
    ull d;
    asm("mul.rn.f32x2 %0, %1, %2;" : "=l"(d) : "l"(a), "l"(b));
    return d;
}

// ---------------- mma helpers ----------------
__device__ __forceinline__ uint32_t smem_u32(const void* p) {
    uint32_t a;
    asm("{ .reg .u64 t; cvta.to.shared.u64 t, %1; cvt.u32.u64 %0, t; }" : "=r"(a) : "l"(p));
    return a;
}
__device__ __forceinline__ void ldm_x4(uint32_t& r0, uint32_t& r1, uint32_t& r2, uint32_t& r3,
                                       uint32_t addr) {
    asm volatile("ldmatrix.sync.aligned.m8n8.x4.shared.b16 {%0,%1,%2,%3}, [%4];"
                 : "=r"(r0), "=r"(r1), "=r"(r2), "=r"(r3) : "r"(addr));
}
__device__ __forceinline__ void mma16816(float* c, const uint32_t* a, const uint32_t* b) {
    asm volatile(
        "mma.sync.aligned.m16n8k16.row.col.f32.bf16.bf16.f32 "
        "{%0,%1,%2,%3}, {%4,%5,%6,%7}, {%8,%9}, {%0,%1,%2,%3};"
        : "+f"(c[0]), "+f"(c[1]), "+f"(c[2]), "+f"(c[3])
        : "r"(a[0]), "r"(a[1]), "r"(a[2]), "r"(a[3]), "r"(b[0]), "r"(b[1]));
}
// XOR swizzle of 16B units within a 256B row (16 units); conflict-free ldmatrix
__host__ __device__ __forceinline__ uint32_t swz(int row, int u) {
    return (u & 8) | ((u ^ row) & 7);
}
__device__ __forceinline__ uint32_t pkbf(__nv_bfloat16 a, __nv_bfloat16 b) {
    __nv_bfloat162 t(a, b);
    return *(uint32_t*)&t;
}
__device__ __forceinline__ void split_bf(float v, __nv_bfloat16& h, __nv_bfloat16& l) {
    h = __float2bfloat16_rn(v);
    l = __float2bfloat16_rn(v - __bfloat162float(h));
}

// smem layout (bytes)
#define SM_AH 0
#define SM_AL 32768
#define SM_WH 65536
#define SM_WL 98304
#define SM_GB 131072               // gemmB total
#define SM_SBUF 131072             // gemmD transpose buffer (64 x 129 float2)
#define SM_GD (131072 + 66048)     // gemmD total = 197120

// ---------------- Kernel 0: split + swizzle weights ----------------
__global__ __launch_bounds__(256) void k_prep(const float* __restrict__ Br,
                                              const float* __restrict__ Bi,
                                              const float* __restrict__ Cr,
                                              const float* __restrict__ Ci) {
    int i = blockIdx.x * 256 + threadIdx.x;    // 16384
    int r = i >> 7, c = i & 127;
    uint32_t off = r * 256 + swz(r, c >> 3) * 16 + (c & 7) * 2;
    // W_B[n=2p+cc][k=h]: n=r, h=c
    {
        int p = r >> 1;
        float v = (r & 1) ? Bi[p * Hn + c] : Br[p * Hn + c];
        __nv_bfloat16 h, l; split_bf(v, h, l);
        *(__nv_bfloat16*)(g_WBh + off) = h;
        *(__nv_bfloat16*)(g_WBl + off) = l;
    }
    // W_C[n=h][k=2p+cc]: n=r(h), k=c
    {
        int p = c >> 1;
        float v = (c & 1) ? -Ci[r * Pn + p] : Cr[r * Pn + p];
        __nv_bfloat16 h, l; split_bf(v, h, l);
        *(__nv_bfloat16*)(g_WCh + off) = h;
        *(__nv_bfloat16*)(g_WCl + off) = l;
    }
}

// ---------------- shared mainloop: 3-pass split-bf16 HMMA ----------------
__device__ __forceinline__ void mma_main(uint32_t smb, int lane, int wm, int wn,
                                         float acc[2][8][4]) {
#pragma unroll
    for (int pass = 0; pass < 3; ++pass) {
        const uint32_t abase = smb + (pass == 2 ? SM_AL : SM_AH);
        const uint32_t wbase = smb + (pass == 1 ? SM_WL : SM_WH);
        const int arow = wm * 32 + (lane & 15);
        const int nrow = wn * 64 + ((lane >> 4) & 1) * 8 + (lane & 7);
#pragma unroll
        for (int ks = 0; ks < 8; ++ks) {
            uint32_t a[2][4];
            const int ua = ks * 2 + (lane >> 4);
#pragma unroll
            for (int mt = 0; mt < 2; ++mt) {
                int row = arow + mt * 16;
                ldm_x4(a[mt][0], a[mt][1], a[mt][2], a[mt][3],
                       abase + row * 256 + swz(row, ua) * 16);
            }
            uint32_t b[8][2];
            const int ub = ks * 2 + ((lane >> 3) & 1);
#pragma unroll
            for (int ng = 0; ng < 4; ++ng) {
                int n = nrow + ng * 16;
                ldm_x4(b[2 * ng][0], b[2 * ng][1], b[2 * ng + 1][0], b[2 * ng + 1][1],
                       wbase + n * 256 + swz(n, ub) * 16);
            }
#pragma unroll
            for (int mt = 0; mt < 2; ++mt)
#pragma unroll
                for (int nt = 0; nt < 8; ++nt)
                    mma16816(acc[mt][nt], a[mt], b[nt]);
        }
    }
}

// ---------------- Kernel 1: gemmB ----------------
// D[l, 2p+c] = sum_h u[l,h]*B_c[p,h]; tile 128 rows per block.
__global__ __launch_bounds__(256) void kb_mma(const float* __restrict__ u) {
    extern __shared__ char sm[];
    const uint32_t smb = smem_u32(sm);
    const int tid = threadIdx.x, lane = tid & 31, wid = tid >> 5;
    const int wm = wid & 3, wn = wid >> 2;

    // stage weights (identity copy, pre-swizzled)
    {
        const uint4* wh = (const uint4*)g_WBh;
        const uint4* wl = (const uint4*)g_WBl;
        uint4* dh = (uint4*)(sm + SM_WH);
        uint4* dl = (uint4*)(sm + SM_WL);
        for (int e = tid; e < 2048; e += 256) { dh[e] = wh[e]; dl[e] = wl[e]; }
    }
    // stage u tile with hi/lo split
    {
        const float4* ug = (const float4*)(u + (size_t)blockIdx.x * 128 * Hn);
        for (int e = tid; e < 4096; e += 256) {
            int row = e >> 5;
            float4 v = ug[e];
            __nv_bfloat16 h0, l0, h1, l1, h2, l2, h3, l3;
            split_bf(v.x, h0, l0); split_bf(v.y, h1, l1);
            split_bf(v.z, h2, l2); split_bf(v.w, h3, l3);
            uint32_t off = row * 256 + swz(row, (e & 31) >> 1) * 16 + (e & 1) * 8;
            *(ull*)(sm + SM_AH + off) = (ull)pkbf(h0, h1) | ((ull)pkbf(h2, h3) << 32);
            *(ull*)(sm + SM_AL + off) = (ull)pkbf(l0, l1) | ((ull)pkbf(l2, l3) << 32);
        }
    }
    __syncthreads();

    float acc[2][8][4];
#pragma unroll
    for (int mt = 0; mt < 2; ++mt)
#pragma unroll
        for (int nt = 0; nt < 8; ++nt)
#pragma unroll
            for (int k = 0; k < 4; ++k) acc[mt][nt][k] = 0.f;

    mma_main(smb, lane, wm, wn, acc);

    // epilogue: (re,im) pairs -> g_Bu[b][p][l][2]
    const int r0 = blockIdx.x * 128 + wm * 32 + (lane >> 2);
#pragma unroll
    for (int mt = 0; mt < 2; ++mt) {
#pragma unroll
        for (int half = 0; half < 2; ++half) {
            int r = r0 + mt * 16 + half * 8;
            int bidx = r >> 13, l = r & 8191;
            float2* dst = (float2*)g_Bu + (size_t)bidx * Pn * Ln + l;
#pragma unroll
            for (int nt = 0; nt < 8; ++nt) {
                int p = wn * 32 + nt * 4 + (lane & 3);
                dst[(size_t)p * Ln] = make_float2(acc[mt][nt][half * 2],
                                                  acc[mt][nt][half * 2 + 1]);
            }
        }
    }
}

// ---------------- Kernel 2: chunked linear-recurrence scan ----------------
__global__ __launch_bounds__(512) void k_recur(const float* __restrict__ A_diag,
                                               const float* __restrict__ steps) {
    const int p = blockIdx.x, b = blockIdx.y;
    const int t = threadIdx.x;

    float a  = fmaxf(A_diag[p], 0.f);
    float s  = 1.f / (1.f + expf(-steps[p]));
    float s2a   = s * s * a;
    float schur = 1.f / (1.f + s2a);
    float m11 = 1.f - s2a * schur;
    float m12 = -s * a * schur;
    float m21 = s * schur;
    float m22 = schur;
    ull M11 = dup2(m11), M12 = dup2(m12), M21 = dup2(m21), M22 = dup2(m22);
    ull C1 = dup2(m11 * s), C2 = dup2(m21 * s);

    const size_t chain = (size_t)(b * Pn + p);
    const ulonglong2* src = (const ulonglong2*)(g_Bu) + chain * (Ln / 2) + t * 8;

    ull f[16];
#pragma unroll
    for (int k = 0; k < 8; ++k) {
        ulonglong2 v = src[k];
        f[2 * k] = v.x; f[2 * k + 1] = v.y;
    }

    ull z = 0, x = 0;
#pragma unroll
    for (int i = 0; i < 16; ++i) {
        ull nz = fma2(M11, z, fma2(M12, x, mul2(C1, f[i])));
        ull nx = fma2(M21, z, fma2(M22, x, mul2(C2, f[i])));
        z = nz; x = nx;
    }

    float q00 = m11, q01 = m12, q10 = m21, q11 = m22;
#pragma unroll
    for (int k = 0; k < 4; ++k) {
        float n00 = q00*q00 + q01*q10, n01 = q00*q01 + q01*q11;
        float n10 = q10*q00 + q11*q10, n11 = q10*q01 + q11*q11;
        q00 = n00; q01 = n01; q10 = n10; q11 = n11;
    }

    __shared__ ulonglong2 sv[512];
    ull vz = z, vx = x;
    int off = 1;
#pragma unroll
    for (int st = 0; st < 9; ++st) {
        sv[t] = make_ulonglong2(vz, vx);
        __syncthreads();
        if (t >= off) {
            ulonglong2 w = sv[t - off];
            ull Q00 = dup2(q00), Q01 = dup2(q01), Q10 = dup2(q10), Q11 = dup2(q11);
            ull nvz = fma2(Q00, w.x, fma2(Q01, w.y, vz));
            ull nvx = fma2(Q10, w.x, fma2(Q11, w.y, vx));
            vz = nvz; vx = nvx;
        }
        __syncthreads();
        float n00 = q00*q00 + q01*q10, n01 = q00*q01 + q01*q11;
        float n10 = q10*q00 + q11*q10, n11 = q10*q01 + q11*q11;
        q00 = n00; q01 = n01; q10 = n10; q11 = n11;
        off <<= 1;
    }
    sv[t] = make_ulonglong2(vz, vx);
    __syncthreads();
    ull z0 = 0, x0 = 0;
    if (t > 0) { ulonglong2 w = sv[t - 1]; z0 = w.x; x0 = w.y; }

    z = z0; x = x0;
#pragma unroll
    for (int i = 0; i < 16; ++i) {
        ull nz = fma2(M11, z, fma2(M12, x, mul2(C1, f[i])));
        ull nx = fma2(M21, z, fma2(M22, x, mul2(C2, f[i])));
        z = nz; x = nx;
        f[i] = x;
    }
    ulonglong2* dst = (ulonglong2*)(g_ys) + chain * (Ln / 2) + t * 8;
#pragma unroll
    for (int k = 0; k < 8; ++k) dst[k] = make_ulonglong2(f[2 * k], f[2 * k + 1]);
}

// ---------------- Kernel 3: gemmD ----------------
// out[l,h] = sum_k ys'[l,k] * W_C[h,k] + D[h]*u[l,h]
__global__ __launch_bounds__(256) void kd_mma(const float* __restrict__ u,
                                              const float* __restrict__ Dv,
                                              float* __restrict__ out) {
    extern __shared__ char sm[];
    const uint32_t smb = smem_u32(sm);
    const int tid = threadIdx.x, lane = tid & 31, wid = tid >> 5;
    const int wm = wid & 3, wn = wid >> 2;
    const int row0 = blockIdx.x * 128;
    const int b = row0 >> 13, l0 = row0 & 8191;

    // stage weights
    {
        const uint4* wh = (const uint4*)g_WCh;
        const uint4* wl = (const uint4*)g_WCl;
        uint4* dh = (uint4*)(sm + SM_WH);
        uint4* dl = (uint4*)(sm + SM_WL);
        for (int e = tid; e < 2048; e += 256) { dh[e] = wh[e]; dl[e] = wl[e]; }
    }
    // pass 1: ys [p][l-tile] -> sbuf (coalesced gmem reads)
    {
        float2* sbuf = (float2*)(sm + SM_SBUF);
        const float2* ysrc = (const float2*)g_ys;
        for (int e = tid; e < 8192; e += 256) {
            int p = e >> 7, l = e & 127;
            sbuf[p * 129 + l] = ysrc[(size_t)(b * Pn + p) * Ln + l0 + l];
        }
    }
    __syncthreads();
    // pass 2: transpose + split -> Ah/Al [l][2p+c]
    {
        const float2* sbuf = (const float2*)(sm + SM_SBUF);
        for (int e = tid; e < 8192; e += 256) {
            int l = e >> 6, p = e & 63;
            float2 v = sbuf[p * 129 + l];
            __nv_bfloat16 hr, lr, hi, li;
            split_bf(v.x, hr, lr); split_bf(v.y, hi, li);
            uint32_t off = l * 256 + swz(l, p >> 2) * 16 + (p & 3) * 4;
            *(uint32_t*)(sm + SM_AH + off) = pkbf(hr, hi);
            *(uint32_t*)(sm + SM_AL + off) = pkbf(lr, li);
        }
    }
    __syncthreads();

    float acc[2][8][4];
#pragma unroll
    for (int mt = 0; mt < 2; ++mt)
#pragma unroll
        for (int nt = 0; nt < 8; ++nt)
#pragma unroll
            for (int k = 0; k < 4; ++k) acc[mt][nt][k] = 0.f;

    mma_main(smb, lane, wm, wn, acc);

    // epilogue: += D*u, store out[l][h]
    const int r0 = row0 + wm * 32 + (lane >> 2);
#pragma unroll
    for (int mt = 0; mt < 2; ++mt) {
#pragma unroll
        for (int half = 0; half < 2; ++half) {
            int r = r0 + mt * 16 + half * 8;
            const float2* urow = (const float2*)u + (size_t)r * 64;
            float2* orow = (float2*)out + (size_t)r * 64;
#pragma unroll
            for (int nt = 0; nt < 8; ++nt) {
                int h2 = wn * 32 + nt * 4 + (lane & 3);   // float2 index (h = 2*h2)
                float2 uu = urow[h2];
                float2 dv = __ldg((const float2*)Dv + h2);
                orow[h2] = make_float2(acc[mt][nt][half * 2] + dv.x * uu.x,
                                       acc[mt][nt][half * 2 + 1] + dv.y * uu.y);
            }
        }
    }
}

// ---------------- launch ----------------
extern "C" void kernel_launch(void* const* d_in, const int* in_sizes, int n_in,
                              void* d_out, int out_size) {
    const float* u     = (const float*)d_in[0];
    const float* A_d   = (const float*)d_in[1];
    const float* Br    = (const float*)d_in[2];
    const float* Bi    = (const float*)d_in[3];
    const float* Cr    = (const float*)d_in[4];
    const float* Ci    = (const float*)d_in[5];
    const float* Dv    = (const float*)d_in[6];
    const float* steps = (const float*)d_in[7];
    float* out = (float*)d_out;

    cudaFuncSetAttribute(kb_mma, cudaFuncAttributeMaxDynamicSharedMemorySize, SM_GB);
    cudaFuncSetAttribute(kd_mma, cudaFuncAttributeMaxDynamicSharedMemorySize, SM_GD);

    k_prep<<<64, 256>>>(Br, Bi, Cr, Ci);
    kb_mma<<<Bn * Ln / 128, 256, SM_GB>>>(u);
    k_recur<<<dim3(Pn, Bn), 512>>>(A_d, steps);
    kd_mma<<<Bn * Ln / 128, 256, SM_GD>>>(u, Dv, out);
}

// round 9
// speedup vs baseline: 1.8961x; 1.1777x over previous
#include <cuda_runtime.h>
#include <cuda_bf16.h>
#include <cstdint>

#define Bn 4
#define Ln 8192
#define Hn 128
#define Pn 64

typedef unsigned long long ull;

// ---------------- global scratch ----------------
__device__ __align__(16) float g_Bu[Bn * Pn * Ln * 2];   // [b][p][l][(re,im)]
__device__ __align__(16) float g_ys[Bn * Pn * Ln * 2];   // [b][p][l][(re,im)]
// pre-split, pre-swizzled bf16 weight tiles (128 rows x 128 cols, 32KB each)
__device__ __align__(16) unsigned char g_WBh[32768];
__device__ __align__(16) unsigned char g_WBl[32768];
__device__ __align__(16) unsigned char g_WCh[32768];
__device__ __align__(16) unsigned char g_WCl[32768];

// ---------------- f32x2 helpers (scan) ----------------
__device__ __forceinline__ ull dup2(float v) {
    ull r; unsigned uv = __float_as_uint(v);
    asm("mov.b64 %0, {%1, %1};" : "=l"(r) : "r"(uv));
    return r;
}
__device__ __forceinline__ ull fma2(ull a, ull b, ull c) {
    ull d;
    asm("fma.rn.f32x2 %0, %1, %2, %3;" : "=l"(d) : "l"(a), "l"(b), "l"(c));
    return d;
}
__device__ __forceinline__ ull mul2(ull a, ull b) {
    ull d;
    asm("mul.rn.f32x2 %0, %1, %2;" : "=l"(d) : "l"(a), "l"(b));
    return d;
}

// ---------------- mma helpers ----------------
__device__ __forceinline__ uint32_t smem_u32(const void* p) {
    uint32_t a;
    asm("{ .reg .u64 t; cvta.to.shared.u64 t, %1; cvt.u32.u64 %0, t; }" : "=r"(a) : "l"(p));
    return a;
}
__device__ __forceinline__ void ldm_x4(uint32_t& r0, uint32_t& r1, uint32_t& r2, uint32_t& r3,
                                       uint32_t addr) {
    asm volatile("ldmatrix.sync.aligned.m8n8.x4.shared.b16 {%0,%1,%2,%3}, [%4];"
                 : "=r"(r0), "=r"(r1), "=r"(r2), "=r"(r3) : "r"(addr));
}
__device__ __forceinline__ void mma16816(float* c, const uint32_t* a, const uint32_t* b) {
    asm volatile(
        "mma.sync.aligned.m16n8k16.row.col.f32.bf16.bf16.f32 "
        "{%0,%1,%2,%3}, {%4,%5,%6,%7}, {%8,%9}, {%0,%1,%2,%3};"
        : "+f"(c[0]), "+f"(c[1]), "+f"(c[2]), "+f"(c[3])
        : "r"(a[0]), "r"(a[1]), "r"(a[2]), "r"(a[3]), "r"(b[0]), "r"(b[1]));
}
// XOR swizzle of 16B units within a 256B row (16 units); conflict-free ldmatrix
__host__ __device__ __forceinline__ uint32_t swz(int row, int u) {
    return (u & 8) | ((u ^ row) & 7);
}
__device__ __forceinline__ uint32_t pkbf(__nv_bfloat16 a, __nv_bfloat16 b) {
    __nv_bfloat162 t(a, b);
    return *(uint32_t*)&t;
}
__device__ __forceinline__ void split_bf(float v, __nv_bfloat16& h, __nv_bfloat16& l) {
    h = __float2bfloat16_rn(v);
    l = __float2bfloat16_rn(v - __bfloat162float(h));
}

// smem layout (bytes) — 256-row A tiles
#define SM_AH 0                    // 256 x 256B = 65536
#define SM_AL 65536
#define SM_WH 131072               // 32768
#define SM_WL 163840
#define SM_GB 196608               // kb total (192 KB)
#define SM_SBUF 131072             // kd: 64 x 129 float2 = 66048 (overlaps W region, used first)
#define SM_GD 197120               // kd total (192.5 KB)

// ---------------- Kernel 0: split + swizzle weights ----------------
__global__ __launch_bounds__(256) void k_prep(const float* __restrict__ Br,
                                              const float* __restrict__ Bi,
                                              const float* __restrict__ Cr,
                                              const float* __restrict__ Ci) {
    int i = blockIdx.x * 256 + threadIdx.x;    // 16384
    int r = i >> 7, c = i & 127;
    uint32_t off = r * 256 + swz(r, c >> 3) * 16 + (c & 7) * 2;
    {
        int p = r >> 1;
        float v = (r & 1) ? Bi[p * Hn + c] : Br[p * Hn + c];
        __nv_bfloat16 h, l; split_bf(v, h, l);
        *(__nv_bfloat16*)(g_WBh + off) = h;
        *(__nv_bfloat16*)(g_WBl + off) = l;
    }
    {
        int p = c >> 1;
        float v = (c & 1) ? -Ci[r * Pn + p] : Cr[r * Pn + p];
        __nv_bfloat16 h, l; split_bf(v, h, l);
        *(__nv_bfloat16*)(g_WCh + off) = h;
        *(__nv_bfloat16*)(g_WCl + off) = l;
    }
}

// ---------------- shared mainloop: 3-pass split-bf16 HMMA, low-reg version ----
// 16 warps: wm = wid&7 (32-row m tile within 256), wn = wid>>3 (64-col n half).
__device__ __forceinline__ void mma_main(uint32_t smb, int lane, int wm, int wn,
                                         float acc[2][8][4]) {
#pragma unroll 1
    for (int pass = 0; pass < 3; ++pass) {
        const uint32_t abase = smb + (pass == 2 ? SM_AL : SM_AH);
        const uint32_t wbase = smb + (pass == 1 ? SM_WL : SM_WH);
        const int arow = wm * 32 + (lane & 15);
        const int nrow = wn * 64 + ((lane >> 4) & 1) * 8 + (lane & 7);
#pragma unroll
        for (int ks = 0; ks < 8; ++ks) {
            uint32_t a[2][4];
            const int ua = ks * 2 + (lane >> 4);
#pragma unroll
            for (int mt = 0; mt < 2; ++mt) {
                int row = arow + mt * 16;
                ldm_x4(a[mt][0], a[mt][1], a[mt][2], a[mt][3],
                       abase + row * 256 + swz(row, ua) * 16);
            }
            const int ub = ks * 2 + ((lane >> 3) & 1);
#pragma unroll
            for (int ng = 0; ng < 4; ++ng) {
                uint32_t b0[2], b1[2];
                int n = nrow + ng * 16;
                ldm_x4(b0[0], b0[1], b1[0], b1[1],
                       wbase + n * 256 + swz(n, ub) * 16);
                mma16816(acc[0][2 * ng], a[0], b0);
                mma16816(acc[0][2 * ng + 1], a[0], b1);
                mma16816(acc[1][2 * ng], a[1], b0);
                mma16816(acc[1][2 * ng + 1], a[1], b1);
            }
        }
    }
}

// ---------------- Kernel 1: gemmB ----------------
// D[l, 2p+c] = sum_h u[l,h]*B_c[p,h]; 256-row tile, 512 threads.
__global__ __launch_bounds__(512) void kb_mma(const float* __restrict__ u) {
    extern __shared__ char sm[];
    const uint32_t smb = smem_u32(sm);
    const int tid = threadIdx.x, lane = tid & 31, wid = tid >> 5;
    const int wm = wid & 7, wn = wid >> 3;

    // stage weights (identity copy, pre-swizzled)
    {
        const uint4* wh = (const uint4*)g_WBh;
        const uint4* wl = (const uint4*)g_WBl;
        uint4* dh = (uint4*)(sm + SM_WH);
        uint4* dl = (uint4*)(sm + SM_WL);
        for (int e = tid; e < 2048; e += 512) { dh[e] = wh[e]; dl[e] = wl[e]; }
    }
    // stage u tile (256 rows) with hi/lo split
    {
        const float4* ug = (const float4*)(u + (size_t)blockIdx.x * 256 * Hn);
        for (int e = tid; e < 8192; e += 512) {
            int row = e >> 5;
            float4 v = ug[e];
            __nv_bfloat16 h0, l0, h1, l1, h2, l2, h3, l3;
            split_bf(v.x, h0, l0); split_bf(v.y, h1, l1);
            split_bf(v.z, h2, l2); split_bf(v.w, h3, l3);
            uint32_t off = row * 256 + swz(row, (e & 31) >> 1) * 16 + (e & 1) * 8;
            *(ull*)(sm + SM_AH + off) = (ull)pkbf(h0, h1) | ((ull)pkbf(h2, h3) << 32);
            *(ull*)(sm + SM_AL + off) = (ull)pkbf(l0, l1) | ((ull)pkbf(l2, l3) << 32);
        }
    }
    __syncthreads();

    float acc[2][8][4];
#pragma unroll
    for (int mt = 0; mt < 2; ++mt)
#pragma unroll
        for (int nt = 0; nt < 8; ++nt)
#pragma unroll
            for (int k = 0; k < 4; ++k) acc[mt][nt][k] = 0.f;

    mma_main(smb, lane, wm, wn, acc);

    // epilogue: transpose via smem, then coalesced store to g_Bu[b][p][l][2]
    __syncthreads();
    float2* tb = (float2*)sm;      // [64 p][257 l-slots] float2 = 131584 B
    const int rl0 = wm * 32 + (lane >> 2);
#pragma unroll
    for (int mt = 0; mt < 2; ++mt)
#pragma unroll
        for (int half = 0; half < 2; ++half) {
            int rl = rl0 + mt * 16 + half * 8;
#pragma unroll
            for (int nt = 0; nt < 8; ++nt) {
                int p = wn * 32 + nt * 4 + (lane & 3);
                tb[p * 257 + rl] = make_float2(acc[mt][nt][half * 2],
                                               acc[mt][nt][half * 2 + 1]);
            }
        }
    __syncthreads();
    {
        const int row0 = blockIdx.x * 256;
        const int b = row0 >> 13, l0 = row0 & 8191;
        ulonglong2* dst = (ulonglong2*)g_Bu;
        for (int e = tid; e < 64 * 128; e += 512) {
            int p = e >> 7, g = e & 127;   // g: 2-l unit
            float2 v0 = tb[p * 257 + 2 * g];
            float2 v1 = tb[p * 257 + 2 * g + 1];
            ulonglong2 w;
            w.x = *(ull*)&v0; w.y = *(ull*)&v1;
            dst[((size_t)(b * Pn + p) * Ln + l0) / 2 + g] = w;
        }
    }
}

// ---------------- Kernel 2: chunked linear-recurrence scan ----------------
__global__ __launch_bounds__(512) void k_recur(const float* __restrict__ A_diag,
                                               const float* __restrict__ steps) {
    const int p = blockIdx.x, b = blockIdx.y;
    const int t = threadIdx.x;

    float a  = fmaxf(A_diag[p], 0.f);
    float s  = 1.f / (1.f + expf(-steps[p]));
    float s2a   = s * s * a;
    float schur = 1.f / (1.f + s2a);
    float m11 = 1.f - s2a * schur;
    float m12 = -s * a * schur;
    float m21 = s * schur;
    float m22 = schur;
    ull M11 = dup2(m11), M12 = dup2(m12), M21 = dup2(m21), M22 = dup2(m22);
    ull C1 = dup2(m11 * s), C2 = dup2(m21 * s);

    const size_t chain = (size_t)(b * Pn + p);
    const ulonglong2* src = (const ulonglong2*)(g_Bu) + chain * (Ln / 2) + t * 8;

    ull f[16];
#pragma unroll
    for (int k = 0; k < 8; ++k) {
        ulonglong2 v = src[k];
        f[2 * k] = v.x; f[2 * k + 1] = v.y;
    }

    ull z = 0, x = 0;
#pragma unroll
    for (int i = 0; i < 16; ++i) {
        ull nz = fma2(M11, z, fma2(M12, x, mul2(C1, f[i])));
        ull nx = fma2(M21, z, fma2(M22, x, mul2(C2, f[i])));
        z = nz; x = nx;
    }

    float q00 = m11, q01 = m12, q10 = m21, q11 = m22;
#pragma unroll
    for (int k = 0; k < 4; ++k) {
        float n00 = q00*q00 + q01*q10, n01 = q00*q01 + q01*q11;
        float n10 = q10*q00 + q11*q10, n11 = q10*q01 + q11*q11;
        q00 = n00; q01 = n01; q10 = n10; q11 = n11;
    }

    __shared__ ulonglong2 sv[512];
    ull vz = z, vx = x;
    int off = 1;
#pragma unroll
    for (int st = 0; st < 9; ++st) {
        sv[t] = make_ulonglong2(vz, vx);
        __syncthreads();
        if (t >= off) {
            ulonglong2 w = sv[t - off];
            ull Q00 = dup2(q00), Q01 = dup2(q01), Q10 = dup2(q10), Q11 = dup2(q11);
            ull nvz = fma2(Q00, w.x, fma2(Q01, w.y, vz));
            ull nvx = fma2(Q10, w.x, fma2(Q11, w.y, vx));
            vz = nvz; vx = nvx;
        }
        __syncthreads();
        float n00 = q00*q00 + q01*q10, n01 = q00*q01 + q01*q11;
        float n10 = q10*q00 + q11*q10, n11 = q10*q01 + q11*q11;
        q00 = n00; q01 = n01; q10 = n10; q11 = n11;
        off <<= 1;
    }
    sv[t] = make_ulonglong2(vz, vx);
    __syncthreads();
    ull z0 = 0, x0 = 0;
    if (t > 0) { ulonglong2 w = sv[t - 1]; z0 = w.x; x0 = w.y; }

    z = z0; x = x0;
#pragma unroll
    for (int i = 0; i < 16; ++i) {
        ull nz = fma2(M11, z, fma2(M12, x, mul2(C1, f[i])));
        ull nx = fma2(M21, z, fma2(M22, x, mul2(C2, f[i])));
        z = nz; x = nx;
        f[i] = x;
    }
    ulonglong2* dst = (ulonglong2*)(g_ys) + chain * (Ln / 2) + t * 8;
#pragma unroll
    for (int k = 0; k < 8; ++k) dst[k] = make_ulonglong2(f[2 * k], f[2 * k + 1]);
}

// ---------------- Kernel 3: gemmD ----------------
// out[l,h] = sum_k ys'[l,k] * W_C[h,k] + D[h]*u[l,h]; 256-row tile, 512 threads.
__global__ __launch_bounds__(512) void kd_mma(const float* __restrict__ u,
                                              const float* __restrict__ Dv,
                                              float* __restrict__ out) {
    extern __shared__ char sm[];
    const uint32_t smb = smem_u32(sm);
    const int tid = threadIdx.x, lane = tid & 31, wid = tid >> 5;
    const int wm = wid & 7, wn = wid >> 3;
    const int row0 = blockIdx.x * 256;
    const int b = row0 >> 13, l0 = row0 & 8191;

    // ys transpose in two 128-l rounds (SBUF overlaps weight region; weights staged after)
    float2* sbuf = (float2*)(sm + SM_SBUF);
    const float2* ysrc = (const float2*)g_ys;
#pragma unroll 1
    for (int half = 0; half < 2; ++half) {
        const int lb = half * 128;
        for (int e = tid; e < 8192; e += 512) {
            int p = e >> 7, l = e & 127;
            sbuf[p * 129 + l] = ysrc[(size_t)(b * Pn + p) * Ln + l0 + lb + l];
        }
        __syncthreads();
        for (int e = tid; e < 8192; e += 512) {
            int l = e >> 6, p = e & 63;
            float2 v = sbuf[p * 129 + l];
            __nv_bfloat16 hr, lr, hi, li;
            split_bf(v.x, hr, lr); split_bf(v.y, hi, li);
            int row = lb + l;
            uint32_t off = row * 256 + swz(row, p >> 2) * 16 + (p & 3) * 4;
            *(uint32_t*)(sm + SM_AH + off) = pkbf(hr, hi);
            *(uint32_t*)(sm + SM_AL + off) = pkbf(lr, li);
        }
        __syncthreads();
    }
    // stage weights (after SBUF is done)
    {
        const uint4* wh = (const uint4*)g_WCh;
        const uint4* wl = (const uint4*)g_WCl;
        uint4* dh = (uint4*)(sm + SM_WH);
        uint4* dl = (uint4*)(sm + SM_WL);
        for (int e = tid; e < 2048; e += 512) { dh[e] = wh[e]; dl[e] = wl[e]; }
    }
    __syncthreads();

    float acc[2][8][4];
#pragma unroll
    for (int mt = 0; mt < 2; ++mt)
#pragma unroll
        for (int nt = 0; nt < 8; ++nt)
#pragma unroll
            for (int k = 0; k < 4; ++k) acc[mt][nt][k] = 0.f;

    mma_main(smb, lane, wm, wn, acc);

    // epilogue: += D*u, store out[l][h] (32B-sector aligned)
    const int r0 = row0 + wm * 32 + (lane >> 2);
#pragma unroll
    for (int mt = 0; mt < 2; ++mt) {
#pragma unroll
        for (int half = 0; half < 2; ++half) {
            int r = r0 + mt * 16 + half * 8;
            const float2* urow = (const float2*)u + (size_t)r * 64;
            float2* orow = (float2*)out + (size_t)r * 64;
#pragma unroll
            for (int nt = 0; nt < 8; ++nt) {
                int h2 = wn * 32 + nt * 4 + (lane & 3);
                float2 uu = urow[h2];
                float2 dv = __ldg((const float2*)Dv + h2);
                orow[h2] = make_float2(acc[mt][nt][half * 2] + dv.x * uu.x,
                                       acc[mt][nt][half * 2 + 1] + dv.y * uu.y);
            }
        }
    }
}

// ---------------- launch ----------------
extern "C" void kernel_launch(void* const* d_in, const int* in_sizes, int n_in,
                              void* d_out, int out_size) {
    const float* u     = (const float*)d_in[0];
    const float* A_d   = (const float*)d_in[1];
    const float* Br    = (const float*)d_in[2];
    const float* Bi    = (const float*)d_in[3];
    const float* Cr    = (const float*)d_in[4];
    const float* Ci    = (const float*)d_in[5];
    const float* Dv    = (const float*)d_in[6];
    const float* steps = (const float*)d_in[7];
    float* out = (float*)d_out;

    cudaFuncSetAttribute(kb_mma, cudaFuncAttributeMaxDynamicSharedMemorySize, SM_GB);
    cudaFuncSetAttribute(kd_mma, cudaFuncAttributeMaxDynamicSharedMemorySize, SM_GD);

    k_prep<<<64, 256>>>(Br, Bi, Cr, Ci);
    kb_mma<<<Bn * Ln / 256, 512, SM_GB>>>(u);
    k_recur<<<dim3(Pn, Bn), 512>>>(A_d, steps);
    kd_mma<<<Bn * Ln / 256, 512, SM_GD>>>(u, Dv, out);
}